// round 5
// baseline (speedup 1.0000x reference)
#include <cuda_runtime.h>
#include <math.h>

namespace {

constexpr int NPTS = 16384;   // N * P

// global scratch
__device__ float g_h2[NPTS * 1024];   // [pt][k(16)][64]
__device__ float g_X0[NPTS * 256];
__device__ float g_X1[NPTS * 256];
__device__ float g_Xf[NPTS * 256];

__device__ __forceinline__ float elu1(float x) { return x > 0.f ? x : expm1f(x); }

// ============================ Kernel A ============================
// per 32 points (2 batches of 16): pts_local, h1, h2 -> g_h2, X0 -> g_X0
constexpr int A_T = 512;
constexpr int A_W1  = 0;       // 192
constexpr int A_B1  = 192;     // 64
constexpr int A_B2  = 256;     // 64
constexpr int A_PLT = 320;     // 768
constexpr int A_W2  = 1088;    // 4096
constexpr int A_WC1 = 5184;    // 12544 (256 x pitch49)
constexpr int A_H1  = 17728;   // 16896 (256 x pitch66)
constexpr int A_SMEM = 34624;  // floats

__global__ void __launch_bounds__(A_T, 1)
kernelA(const float* __restrict__ rep_pt, const float* __restrict__ pts,
        const float* __restrict__ w1,  const float* __restrict__ b1,
        const float* __restrict__ w2,  const float* __restrict__ b2,
        const float* __restrict__ wc1, const float* __restrict__ bc1)
{
    extern __shared__ float sm[];
    float* w1s  = sm + A_W1;
    float* b1s  = sm + A_B1;
    float* b2s  = sm + A_B2;
    float* plT  = sm + A_PLT;
    float* w2s  = sm + A_W2;
    float* wc1s = sm + A_WC1;
    float* h1   = sm + A_H1;

    const int t = threadIdx.x;

    // stage weights once
    for (int i = t; i < 192; i += A_T) w1s[i] = w1[i];
    if (t < 64) { b1s[t] = b1[t]; b2s[t] = b2[t]; }
    for (int i = t; i < 4096; i += A_T) w2s[i] = w2[i];
    for (int i = t; i < 256 * 48; i += A_T) {
        int o = i / 48, m = i - o * 48;
        wc1s[o * 49 + m] = wc1[i];
    }

    for (int b = 0; b < 2; b++) {
        const int pbase = blockIdx.x * 32 + b * 16;
        __syncthreads();   // publishes weights (b=0) / retires h1,plT readers (b=1)

        for (int i = t; i < 768; i += A_T) {
            int g = i / 48, r = i - g * 48, d = r >> 4, k = r & 15;
            int pp = pbase + g;
            plT[i] = pts[(pp * 16 + k) * 3 + d] - rep_pt[pp * 3 + d];
        }
        __syncthreads();

        // A1: h1 (256 rows x 64, pitch 66)
        {
            int row = t >> 1, g = row >> 4, k = row & 15, cb = (t & 1) * 32;
            float p0 = plT[g * 48 + k];
            float p1 = plT[g * 48 + 16 + k];
            float p2 = plT[g * 48 + 32 + k];
            #pragma unroll
            for (int c = 0; c < 32; c++) {
                float a = b1s[cb + c] + p0 * w1s[cb + c] + p1 * w1s[64 + cb + c]
                          + p2 * w1s[128 + cb + c];
                h1[row * 66 + cb + c] = elu1(a);
            }
        }
        __syncthreads();

        // A2: h2 = elu(h1 @ w2 + b2) -> g_h2
        {
            int tc = t & 15, tr = t >> 4;
            float acc[8][4];
            #pragma unroll
            for (int i = 0; i < 8; i++)
                #pragma unroll
                for (int c = 0; c < 4; c++) acc[i][c] = b2s[tc * 4 + c];
            #pragma unroll 8
            for (int j = 0; j < 64; j++) {
                float4 w = *(const float4*)&w2s[j * 64 + tc * 4];
                #pragma unroll
                for (int i = 0; i < 8; i++) {
                    float hv = h1[(tr * 8 + i) * 66 + j];
                    acc[i][0] += hv * w.x; acc[i][1] += hv * w.y;
                    acc[i][2] += hv * w.z; acc[i][3] += hv * w.w;
                }
            }
            #pragma unroll
            for (int i = 0; i < 8; i++) {
                int r = tr * 8 + i;
                float4 o = {elu1(acc[i][0]), elu1(acc[i][1]),
                            elu1(acc[i][2]), elu1(acc[i][3])};
                *(float4*)&g_h2[(size_t)pbase * 1024 + r * 64 + tc * 4] = o;
            }
        }

        // B: X0 = elu(pl_flat @ wc1^T + bc1) -> g_X0
        {
            int g = t >> 5, lane = t & 31;
            float acc[8];
            #pragma unroll
            for (int q = 0; q < 8; q++) acc[q] = bc1[lane + 32 * q];
            const float* pg = plT + g * 48;
            #pragma unroll 8
            for (int m = 0; m < 48; m++) {
                float pv = pg[m];
                #pragma unroll
                for (int q = 0; q < 8; q++) acc[q] += pv * wc1s[(lane + 32 * q) * 49 + m];
            }
            #pragma unroll
            for (int q = 0; q < 8; q++)
                g_X0[(size_t)(pbase + g) * 256 + lane + 32 * q] = elu1(acc[q]);
        }
    }
}

// ============================ GEMM 16384x256x256 ============================
template <int ACT>
__global__ void __launch_bounds__(256, 2)
gemm256(const float* __restrict__ A, const float* __restrict__ W,
        const float* __restrict__ bias, float* __restrict__ C)
{
    __shared__ float As[2][16][132];
    __shared__ float Ws[2][16][128];
    const int tid = threadIdx.x;
    const int bm = blockIdx.x >> 1, bn = blockIdx.x & 1;
    const int tm = tid >> 4, tn = tid & 15;
    const float* Ab = A + (size_t)bm * 128 * 256;
    const float* Wb = W + bn * 128;

    const int f0 = tid, f1 = tid + 256;
    const int ar0 = f0 >> 2, ac0 = (f0 & 3) * 4;
    const int ar1 = f1 >> 2, ac1 = (f1 & 3) * 4;
    const int wr0 = f0 >> 5, wc0 = (f0 & 31) * 4;
    const int wr1 = f1 >> 5, wc1_ = (f1 & 31) * 4;

    float acc[8][8];
    #pragma unroll
    for (int i = 0; i < 8; i++)
        #pragma unroll
        for (int j = 0; j < 8; j++) acc[i][j] = 0.f;

    float4 ra0, ra1, rw0, rw1;
    ra0 = *(const float4*)&Ab[ar0 * 256 + ac0];
    ra1 = *(const float4*)&Ab[ar1 * 256 + ac1];
    rw0 = *(const float4*)&Wb[wr0 * 256 + wc0];
    rw1 = *(const float4*)&Wb[wr1 * 256 + wc1_];
    As[0][ac0 + 0][ar0] = ra0.x; As[0][ac0 + 1][ar0] = ra0.y;
    As[0][ac0 + 2][ar0] = ra0.z; As[0][ac0 + 3][ar0] = ra0.w;
    As[0][ac1 + 0][ar1] = ra1.x; As[0][ac1 + 1][ar1] = ra1.y;
    As[0][ac1 + 2][ar1] = ra1.z; As[0][ac1 + 3][ar1] = ra1.w;
    *(float4*)&Ws[0][wr0][wc0]  = rw0;
    *(float4*)&Ws[0][wr1][wc1_] = rw1;
    __syncthreads();

    ra0 = *(const float4*)&Ab[ar0 * 256 + 16 + ac0];
    ra1 = *(const float4*)&Ab[ar1 * 256 + 16 + ac1];
    rw0 = *(const float4*)&Wb[(16 + wr0) * 256 + wc0];
    rw1 = *(const float4*)&Wb[(16 + wr1) * 256 + wc1_];

    for (int kt = 0; kt < 16; kt++) {
        const int cur = kt & 1;
        if (kt < 15) {
            As[cur ^ 1][ac0 + 0][ar0] = ra0.x; As[cur ^ 1][ac0 + 1][ar0] = ra0.y;
            As[cur ^ 1][ac0 + 2][ar0] = ra0.z; As[cur ^ 1][ac0 + 3][ar0] = ra0.w;
            As[cur ^ 1][ac1 + 0][ar1] = ra1.x; As[cur ^ 1][ac1 + 1][ar1] = ra1.y;
            As[cur ^ 1][ac1 + 2][ar1] = ra1.z; As[cur ^ 1][ac1 + 3][ar1] = ra1.w;
            *(float4*)&Ws[cur ^ 1][wr0][wc0]  = rw0;
            *(float4*)&Ws[cur ^ 1][wr1][wc1_] = rw1;
        }
        if (kt < 14) {
            const int k0 = (kt + 2) * 16;
            ra0 = *(const float4*)&Ab[ar0 * 256 + k0 + ac0];
            ra1 = *(const float4*)&Ab[ar1 * 256 + k0 + ac1];
            rw0 = *(const float4*)&Wb[(k0 + wr0) * 256 + wc0];
            rw1 = *(const float4*)&Wb[(k0 + wr1) * 256 + wc1_];
        }
        #pragma unroll
        for (int kk = 0; kk < 16; kk++) {
            float4 a0 = *(const float4*)&As[cur][kk][tm * 8];
            float4 a1 = *(const float4*)&As[cur][kk][tm * 8 + 4];
            float4 b0 = *(const float4*)&Ws[cur][kk][tn * 8];
            float4 b1 = *(const float4*)&Ws[cur][kk][tn * 8 + 4];
            float av[8] = {a0.x, a0.y, a0.z, a0.w, a1.x, a1.y, a1.z, a1.w};
            float bv[8] = {b0.x, b0.y, b0.z, b0.w, b1.x, b1.y, b1.z, b1.w};
            #pragma unroll
            for (int i = 0; i < 8; i++)
                #pragma unroll
                for (int j = 0; j < 8; j++) acc[i][j] += av[i] * bv[j];
        }
        __syncthreads();
    }

    const int row0 = bm * 128 + tm * 8;
    const int col0 = bn * 128 + tn * 8;
    float4 bs0 = *(const float4*)&bias[col0];
    float4 bs1 = *(const float4*)&bias[col0 + 4];
    float bb[8] = {bs0.x, bs0.y, bs0.z, bs0.w, bs1.x, bs1.y, bs1.z, bs1.w};
    #pragma unroll
    for (int i = 0; i < 8; i++) {
        float v[8];
        #pragma unroll
        for (int j = 0; j < 8; j++) {
            float x = acc[i][j] + bb[j];
            v[j] = ACT ? elu1(x) : x;
        }
        *(float4*)&C[(size_t)(row0 + i) * 256 + col0]     = make_float4(v[0], v[1], v[2], v[3]);
        *(float4*)&C[(size_t)(row0 + i) * 256 + col0 + 4] = make_float4(v[4], v[5], v[6], v[7]);
    }
}

// ============================ Fused D+E ============================
// 32 points/CTA: depthwise (warp-per-point, fc from global) -> smem dw,
// then GEMM 32x128x512 with streamed wpw; bias+ELU+BN epilogue.
constexpr int DE_T = 512;
constexpr int DE_WDW = 0;       // 8448  (64 x pitch132)
constexpr int DE_XF  = 8448;    // 8192  (32 x 256)
constexpr int DE_DW  = 16640;   // 16640 (32 x pitch520)
constexpr int DE_WS  = 33280;   // 4096  (2 x 16 x 128)
constexpr int DE_SMEM = 37376;  // floats = 149504 bytes

__global__ void __launch_bounds__(DE_T, 1)
kernelDE(const float* __restrict__ fts, const float* __restrict__ wdw,
         const float* __restrict__ bdw,
         const float* __restrict__ wpw, const float* __restrict__ bpw,
         const float* __restrict__ bng, const float* __restrict__ bnb,
         const float* __restrict__ bnm, const float* __restrict__ bnv,
         float* __restrict__ out)
{
    extern __shared__ float sm[];
    float* wdwT = sm + DE_WDW;
    float* Xfs  = sm + DE_XF;
    float* dws  = sm + DE_DW;
    float* Ws   = sm + DE_WS;

    const int t = threadIdx.x;
    const int pbase = blockIdx.x * 32;
    const int warp = t >> 5, lane = t & 31;
    const int wrow = t >> 5, wcol = (t & 31) * 4;   // wpw tile staging

    // staging (independent streams; one barrier)
    for (int i = t; i < 8192; i += DE_T) {
        int c = i >> 6, r = i & 63;                 // r = d*16 + k
        wdwT[r * 132 + c] = wdw[i];
    }
    for (int i = t; i < 8192; i += DE_T)
        Xfs[i] = g_Xf[(size_t)pbase * 256 + i];
    *(float4*)&Ws[wrow * 128 + wcol] = *(const float4*)&wpw[wrow * 128 + wcol];
    __syncthreads();

    // ---- phase 1: depthwise, warp per point (2 points per warp) ----
    const int c0 = lane * 4;
    #pragma unroll
    for (int pp = 0; pp < 2; pp++) {
        const int g = warp * 2 + pp;
        const size_t pt = pbase + g;

        float4 fr[16];
        {
            const float* src = (lane < 16)
                ? (g_h2 + pt * 1024 + lane * 4)
                : (fts  + pt * 1024 + (lane - 16) * 4);
            #pragma unroll
            for (int j = 0; j < 16; j++)
                fr[j] = *(const float4*)&src[j * 64];
        }

        float d0[4], d1[4], d2[4], d3[4];
        {
            float4 b0 = *(const float4*)&bdw[(c0 + 0) * 4];
            float4 b1 = *(const float4*)&bdw[(c0 + 1) * 4];
            float4 b2 = *(const float4*)&bdw[(c0 + 2) * 4];
            float4 b3 = *(const float4*)&bdw[(c0 + 3) * 4];
            d0[0]=b0.x; d0[1]=b0.y; d0[2]=b0.z; d0[3]=b0.w;
            d1[0]=b1.x; d1[1]=b1.y; d1[2]=b1.z; d1[3]=b1.w;
            d2[0]=b2.x; d2[1]=b2.y; d2[2]=b2.z; d2[3]=b2.w;
            d3[0]=b3.x; d3[1]=b3.y; d3[2]=b3.z; d3[3]=b3.w;
        }

        #pragma unroll
        for (int i = 0; i < 16; i++) {
            float fx0 = 0.f, fx1 = 0.f, fx2 = 0.f, fx3 = 0.f;
            #pragma unroll
            for (int j = 0; j < 16; j++) {
                float xv = Xfs[g * 256 + i * 16 + j];   // warp broadcast
                fx0 += xv * fr[j].x; fx1 += xv * fr[j].y;
                fx2 += xv * fr[j].z; fx3 += xv * fr[j].w;
            }
            #pragma unroll
            for (int d = 0; d < 4; d++) {
                float4 wd = *(const float4*)&wdwT[(d * 16 + i) * 132 + c0];
                d0[d] += fx0 * wd.x;
                d1[d] += fx1 * wd.y;
                d2[d] += fx2 * wd.z;
                d3[d] += fx3 * wd.w;
            }
        }

        float* dst = &dws[g * 520 + c0 * 4];   // m = c*4 + d
        *(float4*)&dst[0]  = make_float4(d0[0], d0[1], d0[2], d0[3]);
        *(float4*)&dst[4]  = make_float4(d1[0], d1[1], d1[2], d1[3]);
        *(float4*)&dst[8]  = make_float4(d2[0], d2[1], d2[2], d2[3]);
        *(float4*)&dst[12] = make_float4(d3[0], d3[1], d3[2], d3[3]);
    }
    __syncthreads();

    // ---- phase 2: GEMM 32x128x512 (A in smem, W streamed) ----
    const int tm = warp;        // 16 warps -> 2 rows each
    const int tn = lane;        // 4 cols each
    float acc[2][4];
    #pragma unroll
    for (int i = 0; i < 2; i++)
        #pragma unroll
        for (int j = 0; j < 4; j++) acc[i][j] = 0.f;

    float4 rw = *(const float4*)&wpw[(16 + wrow) * 128 + wcol];

    for (int kt = 0; kt < 32; kt++) {
        const int cur = kt & 1;
        if (kt < 31)
            *(float4*)&Ws[(cur ^ 1) * 2048 + wrow * 128 + wcol] = rw;
        if (kt < 30)
            rw = *(const float4*)&wpw[(((kt + 2) * 16) + wrow) * 128 + wcol];

        #pragma unroll
        for (int kk4 = 0; kk4 < 4; kk4++) {
            const int kb = kt * 16 + kk4 * 4;
            float4 a0 = *(const float4*)&dws[(tm * 2 + 0) * 520 + kb];
            float4 a1 = *(const float4*)&dws[(tm * 2 + 1) * 520 + kb];
            float a0v[4] = {a0.x, a0.y, a0.z, a0.w};
            float a1v[4] = {a1.x, a1.y, a1.z, a1.w};
            #pragma unroll
            for (int q = 0; q < 4; q++) {
                float4 w = *(const float4*)&Ws[cur * 2048 + (kk4 * 4 + q) * 128 + tn * 4];
                acc[0][0] += a0v[q] * w.x; acc[0][1] += a0v[q] * w.y;
                acc[0][2] += a0v[q] * w.z; acc[0][3] += a0v[q] * w.w;
                acc[1][0] += a1v[q] * w.x; acc[1][1] += a1v[q] * w.y;
                acc[1][2] += a1v[q] * w.z; acc[1][3] += a1v[q] * w.w;
            }
        }
        __syncthreads();
    }

    // epilogue: bias + ELU + BN
    {
        const int col0 = tn * 4;
        float4 bp = *(const float4*)&bpw[col0];
        float4 gm = *(const float4*)&bng[col0];
        float4 vr = *(const float4*)&bnv[col0];
        float4 mn = *(const float4*)&bnm[col0];
        float4 bt = *(const float4*)&bnb[col0];
        float bb[4] = {bp.x, bp.y, bp.z, bp.w};
        float sc[4] = {gm.x * rsqrtf(vr.x + 1e-5f), gm.y * rsqrtf(vr.y + 1e-5f),
                       gm.z * rsqrtf(vr.z + 1e-5f), gm.w * rsqrtf(vr.w + 1e-5f)};
        float mu[4] = {mn.x, mn.y, mn.z, mn.w};
        float be[4] = {bt.x, bt.y, bt.z, bt.w};
        #pragma unroll
        for (int i = 0; i < 2; i++) {
            float v[4];
            #pragma unroll
            for (int j = 0; j < 4; j++)
                v[j] = (elu1(acc[i][j] + bb[j]) - mu[j]) * sc[j] + be[j];
            const size_t row = (size_t)pbase + tm * 2 + i;
            *(float4*)&out[row * 128 + col0] = make_float4(v[0], v[1], v[2], v[3]);
        }
    }
}

} // namespace

extern "C" void kernel_launch(void* const* d_in, const int* in_sizes, int n_in,
                              void* d_out, int out_size) {
    const float* rep_pt = (const float*)d_in[0];
    const float* pts    = (const float*)d_in[1];
    const float* fts    = (const float*)d_in[2];
    const float* w1     = (const float*)d_in[3];
    const float* b1     = (const float*)d_in[4];
    const float* w2     = (const float*)d_in[5];
    const float* b2     = (const float*)d_in[6];
    const float* wc1    = (const float*)d_in[7];
    const float* bc1    = (const float*)d_in[8];
    const float* wx1    = (const float*)d_in[9];
    const float* bx1    = (const float*)d_in[10];
    const float* wx2    = (const float*)d_in[11];
    const float* bx2    = (const float*)d_in[12];
    const float* wdw    = (const float*)d_in[13];
    const float* bdw    = (const float*)d_in[14];
    const float* wpw    = (const float*)d_in[15];
    const float* bpw    = (const float*)d_in[16];
    const float* bng    = (const float*)d_in[17];
    const float* bnb    = (const float*)d_in[18];
    const float* bnm    = (const float*)d_in[19];
    const float* bnv    = (const float*)d_in[20];
    float* out = (float*)d_out;

    static bool attr_done = false;
    if (!attr_done) {
        cudaFuncSetAttribute(kernelA, cudaFuncAttributeMaxDynamicSharedMemorySize,
                             A_SMEM * (int)sizeof(float));
        cudaFuncSetAttribute(kernelDE, cudaFuncAttributeMaxDynamicSharedMemorySize,
                             DE_SMEM * (int)sizeof(float));
        attr_done = true;
    }

    float* pX0; cudaGetSymbolAddress((void**)&pX0, g_X0);
    float* pX1; cudaGetSymbolAddress((void**)&pX1, g_X1);
    float* pXf; cudaGetSymbolAddress((void**)&pXf, g_Xf);

    kernelA<<<NPTS / 32, A_T, A_SMEM * sizeof(float)>>>(
        rep_pt, pts, w1, b1, w2, b2, wc1, bc1);
    gemm256<1><<<256, 256>>>(pX0, wx1, bx1, pX1);
    gemm256<0><<<256, 256>>>(pX1, wx2, bx2, pXf);
    kernelDE<<<NPTS / 32, DE_T, DE_SMEM * sizeof(float)>>>(
        fts, wdw, bdw, wpw, bpw, bng, bnb, bnm, bnv, out);
}